// round 6
// baseline (speedup 1.0000x reference)
#include <cuda_runtime.h>
#include <cstdint>

#define NN 100000
#define NE 800000
#define FIN 128
#define HID 64
#define NB_SCAN ((NN + 255) / 256)   // 391

static __device__ __constant__ float d_SCALE = 0.70710678118654752440f;
#define BN_EPS 1e-5f

// ---------------- scratch (device globals; no allocation) ----------------
__device__ float g_h0[NN * HID];   // fc output, later h2
__device__ float g_t[NN * HID];    // (h @ w) * dego^-1/2
__device__ float g_h1[NN * HID];   // conv1 output
__device__ int   g_dego[NN];
__device__ int   g_degi[NN];
__device__ int   g_rowptr[NN + 1];
__device__ int   g_cursor[NN];
__device__ int   g_esrc[NE];       // src sorted by dst
__device__ int   g_bsum[NB_SCAN];
__device__ int   g_boff[512];
__device__ float g_sum[HID];
__device__ float g_ssq[HID];
__device__ float g_bna[HID];
__device__ float g_bnc[HID];

// packed fp32x2 FMA
#define FMA2(acc, a, b) \
    asm("fma.rn.f32x2 %0, %1, %2, %0;" : "+l"(acc) : "l"(a), "l"(b))
#define PACK_DUP(dst, fval) \
    asm("mov.b64 %0, {%1, %1};" : "=l"(dst) : "r"(__float_as_uint(fval)))
#define UNPACK2(lo, hi, p) \
    asm("mov.b64 {%0, %1}, %2;" : "=f"(lo), "=f"(hi) : "l"(p))

// ---------------- init ----------------
__global__ void k_init() {
    int i = blockIdx.x * blockDim.x + threadIdx.x;
    if (i < NN) { g_dego[i] = 0; g_degi[i] = 0; }
    if (i < HID) { g_sum[i] = 0.f; g_ssq[i] = 0.f; }
}

__global__ void k_degree(const int* __restrict__ src, const int* __restrict__ dst) {
    int e = blockIdx.x * blockDim.x + threadIdx.x;
    if (e < NE) {
        atomicAdd(&g_dego[src[e]], 1);
        atomicAdd(&g_degi[dst[e]], 1);
    }
}

// ---------------- CSR build: scan of deg_in, then counting-sort fill ----------------
__global__ void k_scanA() {
    __shared__ int sh[256];
    int i = blockIdx.x * 256 + threadIdx.x;
    sh[threadIdx.x] = (i < NN) ? g_degi[i] : 0;
    __syncthreads();
    for (int off = 128; off; off >>= 1) {
        if (threadIdx.x < off) sh[threadIdx.x] += sh[threadIdx.x + off];
        __syncthreads();
    }
    if (threadIdx.x == 0) g_bsum[blockIdx.x] = sh[0];
}

__global__ void k_scanB() {
    __shared__ int sh[512];
    int t = threadIdx.x;
    int v = (t < NB_SCAN) ? g_bsum[t] : 0;
    sh[t] = v;
    __syncthreads();
    for (int off = 1; off < 512; off <<= 1) {
        int a = (t >= off) ? sh[t - off] : 0;
        __syncthreads();
        sh[t] += a;
        __syncthreads();
    }
    g_boff[t] = sh[t] - v;   // exclusive
}

__global__ void k_scanC() {
    __shared__ int sh[256];
    int t = threadIdx.x;
    int i = blockIdx.x * 256 + t;
    int v = (i < NN) ? g_degi[i] : 0;
    sh[t] = v;
    __syncthreads();
    for (int off = 1; off < 256; off <<= 1) {
        int a = (t >= off) ? sh[t - off] : 0;
        __syncthreads();
        sh[t] += a;
        __syncthreads();
    }
    int excl = sh[t] - v + g_boff[blockIdx.x];
    if (i < NN) { g_rowptr[i] = excl; g_cursor[i] = excl; }
    if (i == 0) g_rowptr[NN] = NE;
}

__global__ void k_fill(const int* __restrict__ src, const int* __restrict__ dst) {
    int e = blockIdx.x * blockDim.x + threadIdx.x;
    if (e < NE) {
        int p = atomicAdd(&g_cursor[dst[e]], 1);
        g_esrc[p] = src[e];
    }
}

// ======= packed-fp32 GEMM: C[N,64] = A[N,K] @ W[K,64], 256 thr, 4x8/thr =======
// MODE 0: A = x,    C = g_h0, +bias            (K=128)
// MODE 1: A = g_h0, C = g_t,  * dego^-1/2      (K=64)
// MODE 2: A = g_h1, C = g_t,  * dego^-1/2      (K=64)
template <int MODE>
__global__ __launch_bounds__(256) void k_gemm(const float* __restrict__ Ain,
                                              const float* __restrict__ W,
                                              const float* __restrict__ bias) {
    constexpr int K = (MODE == 0) ? FIN : HID;
    constexpr int KC = 32;

    __shared__ __align__(16) float At[KC][128];
    __shared__ __align__(16) float Ws[KC][HID];

    const float* A = (MODE == 0) ? Ain : ((MODE == 1) ? (const float*)g_h0
                                                      : (const float*)g_h1);
    float* C = (MODE == 0) ? (float*)g_h0 : (float*)g_t;

    const int t = threadIdx.x;
    const int r0 = blockIdx.x * 128;
    const int tr = (t >> 3) * 4;    // 0..124 (4 rows / thread)
    const int tc = (t & 7) * 8;     // 0..56  (8 cols / thread)

    unsigned long long acc[4][4];
#pragma unroll
    for (int i = 0; i < 4; i++)
#pragma unroll
        for (int j = 0; j < 4; j++) acc[i][j] = 0ULL;

    const int arow = t & 127;
    const int ahalf = t >> 7;       // 0/1: which 16-k half this thread loads
    const int rload = min(r0 + arow, NN - 1);
    const float4* A4 = (const float4*)(A + (size_t)rload * K);
    const float4* W4 = (const float4*)W;

    for (int k0 = 0; k0 < K; k0 += KC) {
        __syncthreads();
        float4 v[4];
#pragma unroll
        for (int j = 0; j < 4; j++) v[j] = A4[(k0 >> 2) + ahalf * 4 + j];
#pragma unroll
        for (int j = 0; j < 4; j++) {
            At[ahalf * 16 + 4 * j + 0][arow] = v[j].x;
            At[ahalf * 16 + 4 * j + 1][arow] = v[j].y;
            At[ahalf * 16 + 4 * j + 2][arow] = v[j].z;
            At[ahalf * 16 + 4 * j + 3][arow] = v[j].w;
        }
#pragma unroll
        for (int j = 0; j < 2; j++) {
            int idx = t + j * 256;
            int kk = idx >> 4, c4 = idx & 15;
            *((float4*)&Ws[kk][c4 * 4]) = W4[(k0 + kk) * (HID / 4) + c4];
        }
        __syncthreads();
#pragma unroll
        for (int kk = 0; kk < KC; kk++) {
            unsigned long long bp[4];
            bp[0] = *(const unsigned long long*)&Ws[kk][tc + 0];
            bp[1] = *(const unsigned long long*)&Ws[kk][tc + 2];
            bp[2] = *(const unsigned long long*)&Ws[kk][tc + 4];
            bp[3] = *(const unsigned long long*)&Ws[kk][tc + 6];
            float4 a = *(const float4*)&At[kk][tr];
            float aa[4] = {a.x, a.y, a.z, a.w};
#pragma unroll
            for (int i = 0; i < 4; i++) {
                unsigned long long ad;
                PACK_DUP(ad, aa[i]);
#pragma unroll
                for (int j = 0; j < 4; j++) FMA2(acc[i][j], ad, bp[j]);
            }
        }
    }

#pragma unroll
    for (int i = 0; i < 4; i++) {
        int r = r0 + tr + i;
        if (r < NN) {
            float c0, c1, c2, c3, c4, c5, c6, c7;
            UNPACK2(c0, c1, acc[i][0]);
            UNPACK2(c2, c3, acc[i][1]);
            UNPACK2(c4, c5, acc[i][2]);
            UNPACK2(c6, c7, acc[i][3]);
            float4 o0, o1;
            if (MODE == 0) {
                o0.x = c0 + __ldg(&bias[tc + 0]); o0.y = c1 + __ldg(&bias[tc + 1]);
                o0.z = c2 + __ldg(&bias[tc + 2]); o0.w = c3 + __ldg(&bias[tc + 3]);
                o1.x = c4 + __ldg(&bias[tc + 4]); o1.y = c5 + __ldg(&bias[tc + 5]);
                o1.z = c6 + __ldg(&bias[tc + 6]); o1.w = c7 + __ldg(&bias[tc + 7]);
            } else {
                float sc = rsqrtf((float)max(g_dego[r], 1));
                o0.x = c0 * sc; o0.y = c1 * sc; o0.z = c2 * sc; o0.w = c3 * sc;
                o1.x = c4 * sc; o1.y = c5 * sc; o1.z = c6 * sc; o1.w = c7 * sc;
            }
            *((float4*)&C[(size_t)r * HID + tc]) = o0;
            *((float4*)&C[(size_t)r * HID + tc + 4]) = o1;
        }
    }
}

// ======= CSR gather + combine (+BN partials in MODE 2) =======
// MODE 1: h1 = (h0 + agg*nrmi + b1) * SCALE
// MODE 2: h2 = (h1 + agg*nrmi + b2) * SCALE -> g_h0, accumulate BN sums
template <int MODE>
__global__ __launch_bounds__(256) void k_gather(const float* __restrict__ bias) {
    const int t = threadIdx.x;
    const int node = blockIdx.x * 32 + (t >> 3);   // 32 nodes / block (exact: 3125*32)
    const int c = t & 7;                           // float4 pair index: cols c*8..c*8+7

    const int beg = g_rowptr[node];
    const int end = g_rowptr[node + 1];
    float4 a0 = make_float4(0.f, 0.f, 0.f, 0.f);
    float4 a1 = make_float4(0.f, 0.f, 0.f, 0.f);
    const float4* T4 = (const float4*)g_t;
    for (int e = beg; e < end; e++) {
        int s = __ldg(&g_esrc[e]);
        float4 v0 = T4[s * 16 + c * 2];
        float4 v1 = T4[s * 16 + c * 2 + 1];
        a0.x += v0.x; a0.y += v0.y; a0.z += v0.z; a0.w += v0.w;
        a1.x += v1.x; a1.y += v1.y; a1.z += v1.z; a1.w += v1.w;
    }

    float nd = rsqrtf((float)max(g_degi[node], 1));
    const float4* Hin = (MODE == 1) ? (const float4*)g_h0 : (const float4*)g_h1;
    float4* Hout = (MODE == 1) ? (float4*)g_h1 : (float4*)g_h0;
    float4 h0v = Hin[node * 16 + c * 2];
    float4 h1v = Hin[node * 16 + c * 2 + 1];
    float4 b0 = ((const float4*)bias)[c * 2];
    float4 b1v = ((const float4*)bias)[c * 2 + 1];
    float scl = d_SCALE;
    float4 o0, o1;
    o0.x = (h0v.x + a0.x * nd + b0.x) * scl;
    o0.y = (h0v.y + a0.y * nd + b0.y) * scl;
    o0.z = (h0v.z + a0.z * nd + b0.z) * scl;
    o0.w = (h0v.w + a0.w * nd + b0.w) * scl;
    o1.x = (h1v.x + a1.x * nd + b1v.x) * scl;
    o1.y = (h1v.y + a1.y * nd + b1v.y) * scl;
    o1.z = (h1v.z + a1.z * nd + b1v.z) * scl;
    o1.w = (h1v.w + a1.w * nd + b1v.w) * scl;
    Hout[node * 16 + c * 2] = o0;
    Hout[node * 16 + c * 2 + 1] = o1;

    if (MODE == 2) {
        __shared__ float4 shA[256], shB[256];
        // pass 1: sums
        shA[t] = o0; shB[t] = o1;
        __syncthreads();
        for (int off = 128; off >= 8; off >>= 1) {
            if (t < off) {
                float4 xA = shA[t + off], xB = shB[t + off];
                shA[t].x += xA.x; shA[t].y += xA.y; shA[t].z += xA.z; shA[t].w += xA.w;
                shB[t].x += xB.x; shB[t].y += xB.y; shB[t].z += xB.z; shB[t].w += xB.w;
            }
            __syncthreads();
        }
        if (t < 8) {
            float4 sA = shA[t], sB = shB[t];
            atomicAdd(&g_sum[t * 8 + 0], sA.x);
            atomicAdd(&g_sum[t * 8 + 1], sA.y);
            atomicAdd(&g_sum[t * 8 + 2], sA.z);
            atomicAdd(&g_sum[t * 8 + 3], sA.w);
            atomicAdd(&g_sum[t * 8 + 4], sB.x);
            atomicAdd(&g_sum[t * 8 + 5], sB.y);
            atomicAdd(&g_sum[t * 8 + 6], sB.z);
            atomicAdd(&g_sum[t * 8 + 7], sB.w);
        }
        __syncthreads();
        // pass 2: sums of squares
        float4 q0, q1;
        q0.x = o0.x * o0.x; q0.y = o0.y * o0.y; q0.z = o0.z * o0.z; q0.w = o0.w * o0.w;
        q1.x = o1.x * o1.x; q1.y = o1.y * o1.y; q1.z = o1.z * o1.z; q1.w = o1.w * o1.w;
        shA[t] = q0; shB[t] = q1;
        __syncthreads();
        for (int off = 128; off >= 8; off >>= 1) {
            if (t < off) {
                float4 xA = shA[t + off], xB = shB[t + off];
                shA[t].x += xA.x; shA[t].y += xA.y; shA[t].z += xA.z; shA[t].w += xA.w;
                shB[t].x += xB.x; shB[t].y += xB.y; shB[t].z += xB.z; shB[t].w += xB.w;
            }
            __syncthreads();
        }
        if (t < 8) {
            float4 sA = shA[t], sB = shB[t];
            atomicAdd(&g_ssq[t * 8 + 0], sA.x);
            atomicAdd(&g_ssq[t * 8 + 1], sA.y);
            atomicAdd(&g_ssq[t * 8 + 2], sA.z);
            atomicAdd(&g_ssq[t * 8 + 3], sA.w);
            atomicAdd(&g_ssq[t * 8 + 4], sB.x);
            atomicAdd(&g_ssq[t * 8 + 5], sB.y);
            atomicAdd(&g_ssq[t * 8 + 6], sB.z);
            atomicAdd(&g_ssq[t * 8 + 7], sB.w);
        }
    }
}

__global__ void k_bn_final(const float* __restrict__ gamma, const float* __restrict__ beta) {
    int f = threadIdx.x;
    float mu = g_sum[f] * (1.0f / NN);
    float var = g_ssq[f] * (1.0f / NN) - mu * mu;
    float a = gamma[f] * rsqrtf(var + BN_EPS);
    g_bna[f] = a;
    g_bnc[f] = beta[f] - mu * a;
}

__global__ void k_out(float* __restrict__ out) {
    int idx = blockIdx.x * blockDim.x + threadIdx.x;
    if (idx >= NN * (HID / 4)) return;
    int c4 = idx & 15;
    float4 h = ((const float4*)g_h0)[idx];
    float4 a = ((const float4*)g_bna)[c4];
    float4 c = ((const float4*)g_bnc)[c4];
    float4 r;
    r.x = h.x * a.x + c.x;
    r.y = h.y * a.y + c.y;
    r.z = h.z * a.z + c.z;
    r.w = h.w * a.w + c.w;
    ((float4*)out)[idx] = r;
}

// ---------------- launch ----------------
extern "C" void kernel_launch(void* const* d_in, const int* in_sizes, int n_in,
                              void* d_out, int out_size) {
    const int* src = (const int*)d_in[0];
    const int* dst = (const int*)d_in[1];
    const float* x = (const float*)d_in[2];
    const float* fc_w = (const float*)d_in[3];
    const float* fc_b = (const float*)d_in[4];
    const float* w1 = (const float*)d_in[5];
    const float* b1 = (const float*)d_in[6];
    const float* w2 = (const float*)d_in[7];
    const float* b2 = (const float*)d_in[8];
    const float* gamma = (const float*)d_in[9];
    const float* beta = (const float*)d_in[10];
    float* out = (float*)d_out;

    const int nb_vec = (NN * (HID / 4) + 255) / 256;
    const int nb_edge = (NE + 255) / 256;
    const int nb_gemm = (NN + 127) / 128;     // 782
    const int nb_gath = NN / 32;              // 3125

    k_init<<<NB_SCAN, 256>>>();
    k_degree<<<nb_edge, 256>>>(src, dst);

    // CSR build (dst-sorted edges)
    k_scanA<<<NB_SCAN, 256>>>();
    k_scanB<<<1, 512>>>();
    k_scanC<<<NB_SCAN, 256>>>();
    k_fill<<<nb_edge, 256>>>(src, dst);

    // h0 = x @ fc_w + fc_b
    k_gemm<0><<<nb_gemm, 256>>>(x, fc_w, fc_b);

    // conv1: t = (h0@w1)*dego^-1/2 ; h1 = (h0 + gather(t)*nrmi + b1)*SCALE
    k_gemm<1><<<nb_gemm, 256>>>(nullptr, w1, nullptr);
    k_gather<1><<<nb_gath, 256>>>(b1);

    // conv2: t = (h1@w2)*dego^-1/2 ; h2 = (h1 + gather(t)*nrmi + b2)*SCALE + BN partials
    k_gemm<2><<<nb_gemm, 256>>>(nullptr, w2, nullptr);
    k_gather<2><<<nb_gath, 256>>>(b2);

    k_bn_final<<<1, 64>>>(gamma, beta);
    k_out<<<nb_vec, 256>>>(out);
}

// round 7
// speedup vs baseline: 1.2583x; 1.2583x over previous
#include <cuda_runtime.h>
#include <cstdint>

#define NN 100000
#define NE 800000
#define FIN 128
#define HID 64

static __device__ __constant__ float d_SCALE = 0.70710678118654752440f;
#define BN_EPS 1e-5f

// ---------------- scratch (device globals; no allocation) ----------------
__device__ float g_h0[NN * HID];   // fc output, later reused for h2
__device__ float g_t[NN * HID];    // (h @ w) * dego^-1/2
__device__ float g_agg[NN * HID];  // scatter-add accumulator
__device__ float g_h1[NN * HID];   // conv1 output
__device__ int   g_dego[NN];
__device__ int   g_degi[NN];
__device__ float g_sum[HID];
__device__ float g_ssq[HID];
__device__ float g_bna[HID];
__device__ float g_bnc[HID];

// packed fp32x2 FMA
#define FMA2(acc, a, b) \
    asm("fma.rn.f32x2 %0, %1, %2, %0;" : "+l"(acc) : "l"(a), "l"(b))
#define PACK_DUP(dst, fval) \
    asm("mov.b64 %0, {%1, %1};" : "=l"(dst) : "r"(__float_as_uint(fval)))
#define UNPACK2(lo, hi, p) \
    asm("mov.b64 {%0, %1}, %2;" : "=f"(lo), "=f"(hi) : "l"(p))

// ---------------- init: zero degrees + BN accumulators + agg ----------------
__global__ void k_init() {
    int i = blockIdx.x * blockDim.x + threadIdx.x;
    int T = gridDim.x * blockDim.x;
    for (int j = i; j < NN * (HID / 4); j += T)
        ((float4*)g_agg)[j] = make_float4(0.f, 0.f, 0.f, 0.f);
    if (i < NN) { g_dego[i] = 0; g_degi[i] = 0; }
    if (i < HID) { g_sum[i] = 0.f; g_ssq[i] = 0.f; }
}

// ---------------- degree counting ----------------
__global__ void k_degree(const int* __restrict__ src, const int* __restrict__ dst) {
    int e = blockIdx.x * blockDim.x + threadIdx.x;
    if (e < NE) {
        atomicAdd(&g_dego[src[e]], 1);
        atomicAdd(&g_degi[dst[e]], 1);
    }
}

// ======= packed-fp32 GEMM: C[N,64] = A[N,K] @ W[K,64], 256 thr, 4x8/thr =======
// MODE 0: A = x,    C = g_h0, +bias            (K=128)
// MODE 1: A = g_h0, C = g_t,  * dego^-1/2      (K=64)
// MODE 2: A = g_h1, C = g_t,  * dego^-1/2      (K=64)
template <int MODE>
__global__ __launch_bounds__(256) void k_gemm(const float* __restrict__ Ain,
                                              const float* __restrict__ W,
                                              const float* __restrict__ bias) {
    constexpr int K = (MODE == 0) ? FIN : HID;
    constexpr int KC = 32;

    __shared__ __align__(16) float At[KC][128];
    __shared__ __align__(16) float Ws[KC][HID];

    const float* A = (MODE == 0) ? Ain : ((MODE == 1) ? (const float*)g_h0
                                                      : (const float*)g_h1);
    float* C = (MODE == 0) ? (float*)g_h0 : (float*)g_t;

    const int t = threadIdx.x;
    const int r0 = blockIdx.x * 128;
    const int tr = (t >> 3) * 4;    // 0..124 (4 rows / thread)
    const int tc = (t & 7) * 8;     // 0..56  (8 cols / thread)

    unsigned long long acc[4][4];
#pragma unroll
    for (int i = 0; i < 4; i++)
#pragma unroll
        for (int j = 0; j < 4; j++) acc[i][j] = 0ULL;

    const int arow = t & 127;
    const int ahalf = t >> 7;       // which 16-k half this thread loads
    const int rload = min(r0 + arow, NN - 1);
    const float4* A4 = (const float4*)(A + (size_t)rload * K);
    const float4* W4 = (const float4*)W;

    for (int k0 = 0; k0 < K; k0 += KC) {
        __syncthreads();
        float4 v[4];
#pragma unroll
        for (int j = 0; j < 4; j++) v[j] = A4[(k0 >> 2) + ahalf * 4 + j];
#pragma unroll
        for (int j = 0; j < 4; j++) {
            At[ahalf * 16 + 4 * j + 0][arow] = v[j].x;
            At[ahalf * 16 + 4 * j + 1][arow] = v[j].y;
            At[ahalf * 16 + 4 * j + 2][arow] = v[j].z;
            At[ahalf * 16 + 4 * j + 3][arow] = v[j].w;
        }
#pragma unroll
        for (int j = 0; j < 2; j++) {
            int idx = t + j * 256;
            int kk = idx >> 4, c4 = idx & 15;
            *((float4*)&Ws[kk][c4 * 4]) = W4[(k0 + kk) * (HID / 4) + c4];
        }
        __syncthreads();
#pragma unroll
        for (int kk = 0; kk < KC; kk++) {
            unsigned long long bp[4];
            bp[0] = *(const unsigned long long*)&Ws[kk][tc + 0];
            bp[1] = *(const unsigned long long*)&Ws[kk][tc + 2];
            bp[2] = *(const unsigned long long*)&Ws[kk][tc + 4];
            bp[3] = *(const unsigned long long*)&Ws[kk][tc + 6];
            float4 a = *(const float4*)&At[kk][tr];
            float aa[4] = {a.x, a.y, a.z, a.w};
#pragma unroll
            for (int i = 0; i < 4; i++) {
                unsigned long long ad;
                PACK_DUP(ad, aa[i]);
#pragma unroll
                for (int j = 0; j < 4; j++) FMA2(acc[i][j], ad, bp[j]);
            }
        }
    }

#pragma unroll
    for (int i = 0; i < 4; i++) {
        int r = r0 + tr + i;
        if (r < NN) {
            float c0, c1, c2, c3, c4, c5, c6, c7;
            UNPACK2(c0, c1, acc[i][0]);
            UNPACK2(c2, c3, acc[i][1]);
            UNPACK2(c4, c5, acc[i][2]);
            UNPACK2(c6, c7, acc[i][3]);
            float4 o0, o1;
            if (MODE == 0) {
                o0.x = c0 + __ldg(&bias[tc + 0]); o0.y = c1 + __ldg(&bias[tc + 1]);
                o0.z = c2 + __ldg(&bias[tc + 2]); o0.w = c3 + __ldg(&bias[tc + 3]);
                o1.x = c4 + __ldg(&bias[tc + 4]); o1.y = c5 + __ldg(&bias[tc + 5]);
                o1.z = c6 + __ldg(&bias[tc + 6]); o1.w = c7 + __ldg(&bias[tc + 7]);
            } else {
                float sc = rsqrtf((float)max(g_dego[r], 1));
                o0.x = c0 * sc; o0.y = c1 * sc; o0.z = c2 * sc; o0.w = c3 * sc;
                o1.x = c4 * sc; o1.y = c5 * sc; o1.z = c6 * sc; o1.w = c7 * sc;
            }
            *((float4*)&C[(size_t)r * HID + tc]) = o0;
            *((float4*)&C[(size_t)r * HID + tc + 4]) = o1;
        }
    }
}

// ---------------- edge scatter: agg[dst] += t[src]  (16 threads / edge, v4 red) ----------------
__global__ void k_scatter(const int* __restrict__ src, const int* __restrict__ dst) {
    int idx = blockIdx.x * blockDim.x + threadIdx.x;
    if (idx >= NE * (HID / 4)) return;
    int e = idx >> 4;
    int c = idx & 15;
    int s = __ldg(&src[e]);
    int d = __ldg(&dst[e]);
    float4 v = ((const float4*)g_t)[s * 16 + c];
    float* p = &g_agg[d * HID + c * 4];
    asm volatile("red.global.add.v4.f32 [%0], {%1,%2,%3,%4};"
                 :: "l"(p), "f"(v.x), "f"(v.y), "f"(v.z), "f"(v.w)
                 : "memory");
}

// ------- combine1: h1 = (h0 + agg*nrmi + b1) * SCALE ; re-zero agg for conv2 -------
__global__ void k_combine1(const float* __restrict__ b1) {
    int idx = blockIdx.x * blockDim.x + threadIdx.x;
    if (idx >= NN * (HID / 4)) return;
    int row = idx >> 4;
    int c4 = idx & 15;
    float4 h = ((const float4*)g_h0)[idx];
    float4 a = ((const float4*)g_agg)[idx];
    float4 b = ((const float4*)b1)[c4];
    float nd = rsqrtf((float)max(g_degi[row], 1));
    float s = d_SCALE;
    float4 r;
    r.x = (h.x + a.x * nd + b.x) * s;
    r.y = (h.y + a.y * nd + b.y) * s;
    r.z = (h.z + a.z * nd + b.z) * s;
    r.w = (h.w + a.w * nd + b.w) * s;
    ((float4*)g_h1)[idx] = r;
    ((float4*)g_agg)[idx] = make_float4(0.f, 0.f, 0.f, 0.f);
}

// ------- combine2 + BN partial sums: h2 -> g_h0, accumulate sum/sumsq (float4) -------
__global__ __launch_bounds__(256) void k_combine2_bn(const float* __restrict__ b2) {
    const int T = gridDim.x * blockDim.x;       // multiple of 16
    int tg = blockIdx.x * blockDim.x + threadIdx.x;
    int c4 = tg & 15;                           // constant per thread
    float4 bb = ((const float4*)b2)[c4];
    float scl = d_SCALE;
    float4 s = make_float4(0.f, 0.f, 0.f, 0.f);
    float4 ss = make_float4(0.f, 0.f, 0.f, 0.f);
    for (int idx = tg; idx < NN * (HID / 4); idx += T) {
        int row = idx >> 4;
        float4 h = ((const float4*)g_h1)[idx];
        float4 a = ((const float4*)g_agg)[idx];
        float nd = rsqrtf((float)max(g_degi[row], 1));
        float4 v;
        v.x = (h.x + a.x * nd + bb.x) * scl;
        v.y = (h.y + a.y * nd + bb.y) * scl;
        v.z = (h.z + a.z * nd + bb.z) * scl;
        v.w = (h.w + a.w * nd + bb.w) * scl;
        ((float4*)g_h0)[idx] = v;
        s.x += v.x; s.y += v.y; s.z += v.z; s.w += v.w;
        ss.x += v.x * v.x; ss.y += v.y * v.y; ss.z += v.z * v.z; ss.w += v.w * v.w;
    }
    __shared__ float4 sh[256];
    sh[threadIdx.x] = s;
    __syncthreads();
    if (threadIdx.x < 16) {
        float4 tot = sh[threadIdx.x];
#pragma unroll
        for (int j = 1; j < 16; j++) {
            float4 o = sh[threadIdx.x + j * 16];
            tot.x += o.x; tot.y += o.y; tot.z += o.z; tot.w += o.w;
        }
        atomicAdd(&g_sum[threadIdx.x * 4 + 0], tot.x);
        atomicAdd(&g_sum[threadIdx.x * 4 + 1], tot.y);
        atomicAdd(&g_sum[threadIdx.x * 4 + 2], tot.z);
        atomicAdd(&g_sum[threadIdx.x * 4 + 3], tot.w);
    }
    __syncthreads();
    sh[threadIdx.x] = ss;
    __syncthreads();
    if (threadIdx.x < 16) {
        float4 tot = sh[threadIdx.x];
#pragma unroll
        for (int j = 1; j < 16; j++) {
            float4 o = sh[threadIdx.x + j * 16];
            tot.x += o.x; tot.y += o.y; tot.z += o.z; tot.w += o.w;
        }
        atomicAdd(&g_ssq[threadIdx.x * 4 + 0], tot.x);
        atomicAdd(&g_ssq[threadIdx.x * 4 + 1], tot.y);
        atomicAdd(&g_ssq[threadIdx.x * 4 + 2], tot.z);
        atomicAdd(&g_ssq[threadIdx.x * 4 + 3], tot.w);
    }
}

__global__ void k_bn_final(const float* __restrict__ gamma, const float* __restrict__ beta) {
    int f = threadIdx.x;
    float mu = g_sum[f] * (1.0f / NN);
    float var = g_ssq[f] * (1.0f / NN) - mu * mu;
    float a = gamma[f] * rsqrtf(var + BN_EPS);
    g_bna[f] = a;
    g_bnc[f] = beta[f] - mu * a;
}

__global__ void k_out(float* __restrict__ out) {
    int idx = blockIdx.x * blockDim.x + threadIdx.x;
    if (idx >= NN * (HID / 4)) return;
    int c4 = idx & 15;
    float4 h = ((const float4*)g_h0)[idx];
    float4 a = ((const float4*)g_bna)[c4];
    float4 c = ((const float4*)g_bnc)[c4];
    float4 r;
    r.x = h.x * a.x + c.x;
    r.y = h.y * a.y + c.y;
    r.z = h.z * a.z + c.z;
    r.w = h.w * a.w + c.w;
    ((float4*)out)[idx] = r;
}

// ---------------- launch ----------------
extern "C" void kernel_launch(void* const* d_in, const int* in_sizes, int n_in,
                              void* d_out, int out_size) {
    const int* src = (const int*)d_in[0];
    const int* dst = (const int*)d_in[1];
    const float* x = (const float*)d_in[2];
    const float* fc_w = (const float*)d_in[3];
    const float* fc_b = (const float*)d_in[4];
    const float* w1 = (const float*)d_in[5];
    const float* b1 = (const float*)d_in[6];
    const float* w2 = (const float*)d_in[7];
    const float* b2 = (const float*)d_in[8];
    const float* gamma = (const float*)d_in[9];
    const float* beta = (const float*)d_in[10];
    float* out = (float*)d_out;

    const int nb_vec = (NN * (HID / 4) + 255) / 256;     // 6250
    const int nb_edge = (NE + 255) / 256;
    const int nb_scat = (NE * (HID / 4) + 255) / 256;    // 50000
    const int nb_gemm = (NN + 127) / 128;                // 782

    k_init<<<(NN + 255) / 256, 256>>>();
    k_degree<<<nb_edge, 256>>>(src, dst);

    // h0 = x @ fc_w + fc_b
    k_gemm<0><<<nb_gemm, 256>>>(x, fc_w, fc_b);

    // conv1
    k_gemm<1><<<nb_gemm, 256>>>(nullptr, w1, nullptr);   // t = (h0@w1)*dego^-1/2
    k_scatter<<<nb_scat, 256>>>(src, dst);
    k_combine1<<<nb_vec, 256>>>(b1);                     // h1 + re-zero agg

    // conv2
    k_gemm<2><<<nb_gemm, 256>>>(nullptr, w2, nullptr);   // t = (h1@w2)*dego^-1/2
    k_scatter<<<nb_scat, 256>>>(src, dst);
    k_combine2_bn<<<256, 256>>>(b2);                     // h2 -> g_h0, BN partials

    k_bn_final<<<1, 64>>>(gamma, beta);
    k_out<<<nb_vec, 256>>>(out);
}

// round 8
// speedup vs baseline: 1.4105x; 1.1210x over previous
#include <cuda_runtime.h>
#include <cstdint>

#define NN 100000
#define NE 800000
#define FIN 128
#define HID 64

static __device__ __constant__ float d_SCALE = 0.70710678118654752440f;
#define BN_EPS 1e-5f

// ---------------- scratch (device globals; no allocation) ----------------
__device__ float g_h0[NN * HID];   // fc output, later reused for h2
__device__ float g_t[NN * HID];    // (h @ w) * dego^-1/2
__device__ float g_agg[NN * HID];  // scatter-add accumulator
__device__ float g_h1[NN * HID];   // conv1 output
__device__ int   g_dego[NN];
__device__ int   g_degi[NN];
__device__ float g_sum[HID];
__device__ float g_ssq[HID];
__device__ float g_bna[HID];
__device__ float g_bnc[HID];

// packed fp32x2 FMA
#define FMA2(acc, a, b) \
    asm("fma.rn.f32x2 %0, %1, %2, %0;" : "+l"(acc) : "l"(a), "l"(b))
#define PACK_DUP(dst, fval) \
    asm("mov.b64 %0, {%1, %1};" : "=l"(dst) : "r"(__float_as_uint(fval)))
#define UNPACK2(lo, hi, p) \
    asm("mov.b64 {%0, %1}, %2;" : "=f"(lo), "=f"(hi) : "l"(p))

// ---------------- init: zero degrees + BN accumulators + agg ----------------
__global__ void k_init() {
    int i = blockIdx.x * blockDim.x + threadIdx.x;
    int T = gridDim.x * blockDim.x;
    for (int j = i; j < NN * (HID / 4); j += T)
        ((float4*)g_agg)[j] = make_float4(0.f, 0.f, 0.f, 0.f);
    if (i < NN) { g_dego[i] = 0; g_degi[i] = 0; }
    if (i < HID) { g_sum[i] = 0.f; g_ssq[i] = 0.f; }
}

// ---------------- degree counting ----------------
__global__ void k_degree(const int* __restrict__ src, const int* __restrict__ dst) {
    int e = blockIdx.x * blockDim.x + threadIdx.x;
    if (e < NE) {
        atomicAdd(&g_dego[src[e]], 1);
        atomicAdd(&g_degi[dst[e]], 1);
    }
}

// ======= packed-fp32 GEMM: C[N,64] = A[N,K] @ W[K,64], 256 thr, 4x8/thr =======
// Bank-conflict-free mapping: lane -> contiguous rows (A LDS.128 conflict-free),
// warp -> column group (B LDS.64 full-warp broadcast).
// MODE 0: A = x,    C = g_h0, +bias            (K=128)
// MODE 1: A = g_h0, C = g_t,  * dego^-1/2      (K=64)
// MODE 2: A = g_h1, C = g_t,  * dego^-1/2      (K=64)
template <int MODE>
__global__ __launch_bounds__(256) void k_gemm(const float* __restrict__ Ain,
                                              const float* __restrict__ W,
                                              const float* __restrict__ bias) {
    constexpr int K = (MODE == 0) ? FIN : HID;
    constexpr int KC = 32;

    __shared__ __align__(16) float At[KC][128];
    __shared__ __align__(16) float Ws[KC][HID];

    const float* A = (MODE == 0) ? Ain : ((MODE == 1) ? (const float*)g_h0
                                                      : (const float*)g_h1);
    float* C = (MODE == 0) ? (float*)g_h0 : (float*)g_t;

    const int t = threadIdx.x;
    const int lane = t & 31;
    const int warp = t >> 5;
    const int r0 = blockIdx.x * 128;
    const int tr = lane * 4;        // 4 consecutive rows per lane -> A conflict-free
    const int tc = warp * 8;        // 8 cols per warp -> B broadcast

    unsigned long long acc[4][4];
#pragma unroll
    for (int i = 0; i < 4; i++)
#pragma unroll
        for (int j = 0; j < 4; j++) acc[i][j] = 0ULL;

    const int arow = t & 127;
    const int ahalf = t >> 7;       // which 16-k half this thread loads
    const int rload = min(r0 + arow, NN - 1);
    const float4* A4 = (const float4*)(A + (size_t)rload * K);
    const float4* W4 = (const float4*)W;

    for (int k0 = 0; k0 < K; k0 += KC) {
        __syncthreads();
        float4 v[4];
#pragma unroll
        for (int j = 0; j < 4; j++) v[j] = A4[(k0 >> 2) + ahalf * 4 + j];
#pragma unroll
        for (int j = 0; j < 4; j++) {
            At[ahalf * 16 + 4 * j + 0][arow] = v[j].x;
            At[ahalf * 16 + 4 * j + 1][arow] = v[j].y;
            At[ahalf * 16 + 4 * j + 2][arow] = v[j].z;
            At[ahalf * 16 + 4 * j + 3][arow] = v[j].w;
        }
#pragma unroll
        for (int j = 0; j < 2; j++) {
            int idx = t + j * 256;
            int kk = idx >> 4, c4 = idx & 15;
            *((float4*)&Ws[kk][c4 * 4]) = W4[(k0 + kk) * (HID / 4) + c4];
        }
        __syncthreads();
#pragma unroll
        for (int kk = 0; kk < KC; kk++) {
            // broadcast loads: same address across the warp
            unsigned long long bp[4];
            bp[0] = *(const unsigned long long*)&Ws[kk][tc + 0];
            bp[1] = *(const unsigned long long*)&Ws[kk][tc + 2];
            bp[2] = *(const unsigned long long*)&Ws[kk][tc + 4];
            bp[3] = *(const unsigned long long*)&Ws[kk][tc + 6];
            // contiguous per-warp 512B read: conflict-free
            float4 a = *(const float4*)&At[kk][tr];
            float aa[4] = {a.x, a.y, a.z, a.w};
#pragma unroll
            for (int i = 0; i < 4; i++) {
                unsigned long long ad;
                PACK_DUP(ad, aa[i]);
#pragma unroll
                for (int j = 0; j < 4; j++) FMA2(acc[i][j], ad, bp[j]);
            }
        }
    }

#pragma unroll
    for (int i = 0; i < 4; i++) {
        int r = r0 + tr + i;
        if (r < NN) {
            float c0, c1, c2, c3, c4, c5, c6, c7;
            UNPACK2(c0, c1, acc[i][0]);
            UNPACK2(c2, c3, acc[i][1]);
            UNPACK2(c4, c5, acc[i][2]);
            UNPACK2(c6, c7, acc[i][3]);
            float4 o0, o1;
            if (MODE == 0) {
                o0.x = c0 + __ldg(&bias[tc + 0]); o0.y = c1 + __ldg(&bias[tc + 1]);
                o0.z = c2 + __ldg(&bias[tc + 2]); o0.w = c3 + __ldg(&bias[tc + 3]);
                o1.x = c4 + __ldg(&bias[tc + 4]); o1.y = c5 + __ldg(&bias[tc + 5]);
                o1.z = c6 + __ldg(&bias[tc + 6]); o1.w = c7 + __ldg(&bias[tc + 7]);
            } else {
                float sc = rsqrtf((float)max(g_dego[r], 1));
                o0.x = c0 * sc; o0.y = c1 * sc; o0.z = c2 * sc; o0.w = c3 * sc;
                o1.x = c4 * sc; o1.y = c5 * sc; o1.z = c6 * sc; o1.w = c7 * sc;
            }
            *((float4*)&C[(size_t)r * HID + tc]) = o0;
            *((float4*)&C[(size_t)r * HID + tc + 4]) = o1;
        }
    }
}

// ---------------- edge scatter: agg[dst] += t[src]  (16 threads / edge, v4 red) ----------------
__global__ void k_scatter(const int* __restrict__ src, const int* __restrict__ dst) {
    int idx = blockIdx.x * blockDim.x + threadIdx.x;
    if (idx >= NE * (HID / 4)) return;
    int e = idx >> 4;
    int c = idx & 15;
    int s = __ldg(&src[e]);
    int d = __ldg(&dst[e]);
    float4 v = ((const float4*)g_t)[s * 16 + c];
    float* p = &g_agg[d * HID + c * 4];
    asm volatile("red.global.add.v4.f32 [%0], {%1,%2,%3,%4};"
                 :: "l"(p), "f"(v.x), "f"(v.y), "f"(v.z), "f"(v.w)
                 : "memory");
}

// ------- combine1: h1 = (h0 + agg*nrmi + b1) * SCALE ; re-zero agg for conv2 -------
__global__ void k_combine1(const float* __restrict__ b1) {
    int idx = blockIdx.x * blockDim.x + threadIdx.x;
    if (idx >= NN * (HID / 4)) return;
    int row = idx >> 4;
    int c4 = idx & 15;
    float4 h = ((const float4*)g_h0)[idx];
    float4 a = ((const float4*)g_agg)[idx];
    float4 b = ((const float4*)b1)[c4];
    float nd = rsqrtf((float)max(g_degi[row], 1));
    float s = d_SCALE;
    float4 r;
    r.x = (h.x + a.x * nd + b.x) * s;
    r.y = (h.y + a.y * nd + b.y) * s;
    r.z = (h.z + a.z * nd + b.z) * s;
    r.w = (h.w + a.w * nd + b.w) * s;
    ((float4*)g_h1)[idx] = r;
    ((float4*)g_agg)[idx] = make_float4(0.f, 0.f, 0.f, 0.f);
}

// ------- combine2 + BN partial sums: h2 -> g_h0, accumulate sum/sumsq (float4) -------
__global__ __launch_bounds__(256) void k_combine2_bn(const float* __restrict__ b2) {
    const int T = gridDim.x * blockDim.x;       // multiple of 16
    int tg = blockIdx.x * blockDim.x + threadIdx.x;
    int c4 = tg & 15;                           // constant per thread
    float4 bb = ((const float4*)b2)[c4];
    float scl = d_SCALE;
    float4 s = make_float4(0.f, 0.f, 0.f, 0.f);
    float4 ss = make_float4(0.f, 0.f, 0.f, 0.f);
    for (int idx = tg; idx < NN * (HID / 4); idx += T) {
        int row = idx >> 4;
        float4 h = ((const float4*)g_h1)[idx];
        float4 a = ((const float4*)g_agg)[idx];
        float nd = rsqrtf((float)max(g_degi[row], 1));
        float4 v;
        v.x = (h.x + a.x * nd + bb.x) * scl;
        v.y = (h.y + a.y * nd + bb.y) * scl;
        v.z = (h.z + a.z * nd + bb.z) * scl;
        v.w = (h.w + a.w * nd + bb.w) * scl;
        ((float4*)g_h0)[idx] = v;
        s.x += v.x; s.y += v.y; s.z += v.z; s.w += v.w;
        ss.x += v.x * v.x; ss.y += v.y * v.y; ss.z += v.z * v.z; ss.w += v.w * v.w;
    }
    __shared__ float4 sh[256];
    sh[threadIdx.x] = s;
    __syncthreads();
    if (threadIdx.x < 16) {
        float4 tot = sh[threadIdx.x];
#pragma unroll
        for (int j = 1; j < 16; j++) {
            float4 o = sh[threadIdx.x + j * 16];
            tot.x += o.x; tot.y += o.y; tot.z += o.z; tot.w += o.w;
        }
        atomicAdd(&g_sum[threadIdx.x * 4 + 0], tot.x);
        atomicAdd(&g_sum[threadIdx.x * 4 + 1], tot.y);
        atomicAdd(&g_sum[threadIdx.x * 4 + 2], tot.z);
        atomicAdd(&g_sum[threadIdx.x * 4 + 3], tot.w);
    }
    __syncthreads();
    sh[threadIdx.x] = ss;
    __syncthreads();
    if (threadIdx.x < 16) {
        float4 tot = sh[threadIdx.x];
#pragma unroll
        for (int j = 1; j < 16; j++) {
            float4 o = sh[threadIdx.x + j * 16];
            tot.x += o.x; tot.y += o.y; tot.z += o.z; tot.w += o.w;
        }
        atomicAdd(&g_ssq[threadIdx.x * 4 + 0], tot.x);
        atomicAdd(&g_ssq[threadIdx.x * 4 + 1], tot.y);
        atomicAdd(&g_ssq[threadIdx.x * 4 + 2], tot.z);
        atomicAdd(&g_ssq[threadIdx.x * 4 + 3], tot.w);
    }
}

__global__ void k_bn_final(const float* __restrict__ gamma, const float* __restrict__ beta) {
    int f = threadIdx.x;
    float mu = g_sum[f] * (1.0f / NN);
    float var = g_ssq[f] * (1.0f / NN) - mu * mu;
    float a = gamma[f] * rsqrtf(var + BN_EPS);
    g_bna[f] = a;
    g_bnc[f] = beta[f] - mu * a;
}

__global__ void k_out(float* __restrict__ out) {
    int idx = blockIdx.x * blockDim.x + threadIdx.x;
    if (idx >= NN * (HID / 4)) return;
    int c4 = idx & 15;
    float4 h = ((const float4*)g_h0)[idx];
    float4 a = ((const float4*)g_bna)[c4];
    float4 c = ((const float4*)g_bnc)[c4];
    float4 r;
    r.x = h.x * a.x + c.x;
    r.y = h.y * a.y + c.y;
    r.z = h.z * a.z + c.z;
    r.w = h.w * a.w + c.w;
    ((float4*)out)[idx] = r;
}

// ---------------- launch ----------------
extern "C" void kernel_launch(void* const* d_in, const int* in_sizes, int n_in,
                              void* d_out, int out_size) {
    const int* src = (const int*)d_in[0];
    const int* dst = (const int*)d_in[1];
    const float* x = (const float*)d_in[2];
    const float* fc_w = (const float*)d_in[3];
    const float* fc_b = (const float*)d_in[4];
    const float* w1 = (const float*)d_in[5];
    const float* b1 = (const float*)d_in[6];
    const float* w2 = (const float*)d_in[7];
    const float* b2 = (const float*)d_in[8];
    const float* gamma = (const float*)d_in[9];
    const float* beta = (const float*)d_in[10];
    float* out = (float*)d_out;

    const int nb_vec = (NN * (HID / 4) + 255) / 256;     // 6250
    const int nb_edge = (NE + 255) / 256;
    const int nb_scat = (NE * (HID / 4) + 255) / 256;    // 50000
    const int nb_gemm = (NN + 127) / 128;                // 782

    k_init<<<(NN + 255) / 256, 256>>>();
    k_degree<<<nb_edge, 256>>>(src, dst);

    // h0 = x @ fc_w + fc_b
    k_gemm<0><<<nb_gemm, 256>>>(x, fc_w, fc_b);

    // conv1
    k_gemm<1><<<nb_gemm, 256>>>(nullptr, w1, nullptr);   // t = (h0@w1)*dego^-1/2
    k_scatter<<<nb_scat, 256>>>(src, dst);
    k_combine1<<<nb_vec, 256>>>(b1);                     // h1 + re-zero agg

    // conv2
    k_gemm<2><<<nb_gemm, 256>>>(nullptr, w2, nullptr);   // t = (h1@w2)*dego^-1/2
    k_scatter<<<nb_scat, 256>>>(src, dst);
    k_combine2_bn<<<256, 256>>>(b2);                     // h2 -> g_h0, BN partials

    k_bn_final<<<1, 64>>>(gamma, beta);
    k_out<<<nb_vec, 256>>>(out);
}

// round 10
// speedup vs baseline: 1.4439x; 1.0237x over previous
#include <cuda_runtime.h>
#include <cstdint>

#define NN 100000
#define NE 800000
#define FIN 128
#define HID 64

static __device__ __constant__ float d_SCALE = 0.70710678118654752440f;
#define BN_EPS 1e-5f

// ---------------- scratch (device globals; no allocation) ----------------
__device__ float g_h0[NN * HID];   // fc output, later reused for h2
__device__ float g_t[NN * HID];    // (h @ w) * dego^-1/2
__device__ float g_agg[NN * HID];  // scatter-add accumulator
__device__ float g_h1[NN * HID];   // conv1 output
__device__ int   g_dego[NN];
__device__ int   g_degi[NN];
__device__ float g_sum[HID];
__device__ float g_ssq[HID];
__device__ float g_bna[HID];
__device__ float g_bnc[HID];

// packed fp32x2 FMA
#define FMA2(acc, a, b) \
    asm("fma.rn.f32x2 %0, %1, %2, %0;" : "+l"(acc) : "l"(a), "l"(b))
#define PACK_DUP(dst, fval) \
    asm("mov.b64 %0, {%1, %1};" : "=l"(dst) : "r"(__float_as_uint(fval)))
#define UNPACK2(lo, hi, p) \
    asm("mov.b64 {%0, %1}, %2;" : "=f"(lo), "=f"(hi) : "l"(p))

// ---------------- init: zero agg + degrees + BN accumulators ----------------
__global__ void k_init() {
    int i = blockIdx.x * blockDim.x + threadIdx.x;
    if (i < NN * (HID / 4))
        ((float4*)g_agg)[i] = make_float4(0.f, 0.f, 0.f, 0.f);
    if (i < NN) { g_dego[i] = 0; g_degi[i] = 0; }
    if (i < HID) { g_sum[i] = 0.f; g_ssq[i] = 0.f; }
}

// ---------------- degree counting ----------------
__global__ void k_degree(const int* __restrict__ src, const int* __restrict__ dst) {
    int e = blockIdx.x * blockDim.x + threadIdx.x;
    if (e < NE) {
        atomicAdd(&g_dego[src[e]], 1);
        atomicAdd(&g_degi[dst[e]], 1);
    }
}

// ======= packed-fp32 GEMM: C[N,64] = A[N,K] @ W[K,64], 256 thr =======
// KC=64 staging: K=64 -> single chunk (one sync pair); K=128 -> 2 chunks
// with register prefetch of chunk 1 during chunk 0 compute.
// lane -> 4 contiguous rows (A LDS.128 conflict-free), warp -> 8 cols (B broadcast).
// MODE 0: A = x,    C = g_h0, +bias            (K=128)
// MODE 1: A = g_h0, C = g_t,  * dego^-1/2      (K=64)
// MODE 2: A = g_h1, C = g_t,  * dego^-1/2      (K=64)
template <int MODE>
__global__ __launch_bounds__(256) void k_gemm(const float* __restrict__ Ain,
                                              const float* __restrict__ W,
                                              const float* __restrict__ bias) {
    constexpr int K = (MODE == 0) ? FIN : HID;
    constexpr int NCH = K / 64;

    __shared__ __align__(16) float At[64][128];   // 32 KB
    __shared__ __align__(16) float Ws[64][HID];   // 16 KB

    const float* A = (MODE == 0) ? Ain : ((MODE == 1) ? (const float*)g_h0
                                                      : (const float*)g_h1);
    float* C = (MODE == 0) ? (float*)g_h0 : (float*)g_t;

    const int t = threadIdx.x;
    const int lane = t & 31;
    const int warp = t >> 5;
    const int r0 = blockIdx.x * 128;
    const int tr = lane * 4;        // 4 consecutive rows -> A conflict-free
    const int tc = warp * 8;        // 8 cols per warp -> B broadcast

    unsigned long long acc[4][4];
#pragma unroll
    for (int i = 0; i < 4; i++)
#pragma unroll
        for (int j = 0; j < 4; j++) acc[i][j] = 0ULL;

    const int arow = t & 127;
    const int ahalf = t >> 7;       // which 32-float half of the 64-k chunk
    const int rload = min(r0 + arow, NN - 1);
    const float4* A4 = (const float4*)(A + (size_t)rload * K);
    const float4* W4 = (const float4*)W;

    float4 bb0, bb1;
    if (MODE == 0) {
        bb0 = __ldg((const float4*)&bias[tc]);
        bb1 = __ldg((const float4*)&bias[tc + 4]);
    }

    // prefetch chunk 0
    float4 va[8], vw[4];
#pragma unroll
    for (int j = 0; j < 8; j++) va[j] = A4[ahalf * 8 + j];
#pragma unroll
    for (int j = 0; j < 4; j++) {
        int idx = t + j * 256;
        vw[j] = W4[(idx >> 4) * (HID / 4) + (idx & 15)];
    }

#pragma unroll
    for (int ch = 0; ch < NCH; ch++) {
        if (ch > 0) __syncthreads();
        // store staged chunk to smem
#pragma unroll
        for (int j = 0; j < 8; j++) {
            At[ahalf * 32 + 4 * j + 0][arow] = va[j].x;
            At[ahalf * 32 + 4 * j + 1][arow] = va[j].y;
            At[ahalf * 32 + 4 * j + 2][arow] = va[j].z;
            At[ahalf * 32 + 4 * j + 3][arow] = va[j].w;
        }
#pragma unroll
        for (int j = 0; j < 4; j++) {
            int idx = t + j * 256;
            *((float4*)&Ws[idx >> 4][(idx & 15) * 4]) = vw[j];
        }
        __syncthreads();
        // prefetch next chunk while computing this one
        if (ch + 1 < NCH) {
#pragma unroll
            for (int j = 0; j < 8; j++) va[j] = A4[16 + ahalf * 8 + j];
#pragma unroll
            for (int j = 0; j < 4; j++) {
                int idx = t + j * 256;
                vw[j] = W4[(64 + (idx >> 4)) * (HID / 4) + (idx & 15)];
            }
        }
#pragma unroll 16
        for (int kk = 0; kk < 64; kk++) {
            unsigned long long bp[4];
            bp[0] = *(const unsigned long long*)&Ws[kk][tc + 0];
            bp[1] = *(const unsigned long long*)&Ws[kk][tc + 2];
            bp[2] = *(const unsigned long long*)&Ws[kk][tc + 4];
            bp[3] = *(const unsigned long long*)&Ws[kk][tc + 6];
            float4 a = *(const float4*)&At[kk][tr];
            float aa[4] = {a.x, a.y, a.z, a.w};
#pragma unroll
            for (int i = 0; i < 4; i++) {
                unsigned long long ad;
                PACK_DUP(ad, aa[i]);
#pragma unroll
                for (int j = 0; j < 4; j++) FMA2(acc[i][j], ad, bp[j]);
            }
        }
    }

#pragma unroll
    for (int i = 0; i < 4; i++) {
        int r = r0 + tr + i;
        if (r < NN) {
            float c0, c1, c2, c3, c4, c5, c6, c7;
            UNPACK2(c0, c1, acc[i][0]);
            UNPACK2(c2, c3, acc[i][1]);
            UNPACK2(c4, c5, acc[i][2]);
            UNPACK2(c6, c7, acc[i][3]);
            float4 o0, o1;
            if (MODE == 0) {
                o0.x = c0 + bb0.x; o0.y = c1 + bb0.y;
                o0.z = c2 + bb0.z; o0.w = c3 + bb0.w;
                o1.x = c4 + bb1.x; o1.y = c5 + bb1.y;
                o1.z = c6 + bb1.z; o1.w = c7 + bb1.w;
            } else {
                float sc = rsqrtf((float)max(g_dego[r], 1));
                o0.x = c0 * sc; o0.y = c1 * sc; o0.z = c2 * sc; o0.w = c3 * sc;
                o1.x = c4 * sc; o1.y = c5 * sc; o1.z = c6 * sc; o1.w = c7 * sc;
            }
            *((float4*)&C[(size_t)r * HID + tc]) = o0;
            *((float4*)&C[(size_t)r * HID + tc + 4]) = o1;
        }
    }
}

// ---------------- edge scatter: agg[dst] += t[src]  (16 threads / edge, v4 red) ----------------
__global__ void k_scatter(const int* __restrict__ src, const int* __restrict__ dst) {
    int idx = blockIdx.x * blockDim.x + threadIdx.x;
    if (idx >= NE * (HID / 4)) return;
    int e = idx >> 4;
    int c = idx & 15;
    int s = __ldg(&src[e]);
    int d = __ldg(&dst[e]);
    float4 v = ((const float4*)g_t)[s * 16 + c];
    float* p = &g_agg[d * HID + c * 4];
    asm volatile("red.global.add.v4.f32 [%0], {%1,%2,%3,%4};"
                 :: "l"(p), "f"(v.x), "f"(v.y), "f"(v.z), "f"(v.w)
                 : "memory");
}

// ------- combine1: h1 = (h0 + agg*nrmi + b1) * SCALE ; re-zero agg for conv2 -------
__global__ void k_combine1(const float* __restrict__ b1) {
    int idx = blockIdx.x * blockDim.x + threadIdx.x;
    if (idx >= NN * (HID / 4)) return;
    int row = idx >> 4;
    int c4 = idx & 15;
    float4 h = ((const float4*)g_h0)[idx];
    float4 a = ((const float4*)g_agg)[idx];
    float4 b = ((const float4*)b1)[c4];
    float nd = rsqrtf((float)max(g_degi[row], 1));
    float s = d_SCALE;
    float4 r;
    r.x = (h.x + a.x * nd + b.x) * s;
    r.y = (h.y + a.y * nd + b.y) * s;
    r.z = (h.z + a.z * nd + b.z) * s;
    r.w = (h.w + a.w * nd + b.w) * s;
    ((float4*)g_h1)[idx] = r;
    ((float4*)g_agg)[idx] = make_float4(0.f, 0.f, 0.f, 0.f);
}

// ------- combine2 + BN partial sums: h2 -> g_h0, accumulate sum/sumsq (float4) -------
__global__ __launch_bounds__(256) void k_combine2_bn(const float* __restrict__ b2) {
    const int T = gridDim.x * blockDim.x;       // multiple of 16
    int tg = blockIdx.x * blockDim.x + threadIdx.x;
    int c4 = tg & 15;                           // constant per thread
    float4 bb = ((const float4*)b2)[c4];
    float scl = d_SCALE;
    float4 s = make_float4(0.f, 0.f, 0.f, 0.f);
    float4 ss = make_float4(0.f, 0.f, 0.f, 0.f);
    for (int idx = tg; idx < NN * (HID / 4); idx += T) {
        int row = idx >> 4;
        float4 h = ((const float4*)g_h1)[idx];
        float4 a = ((const float4*)g_agg)[idx];
        float nd = rsqrtf((float)max(g_degi[row], 1));
        float4 v;
        v.x = (h.x + a.x * nd + bb.x) * scl;
        v.y = (h.y + a.y * nd + bb.y) * scl;
        v.z = (h.z + a.z * nd + bb.z) * scl;
        v.w = (h.w + a.w * nd + bb.w) * scl;
        ((float4*)g_h0)[idx] = v;
        s.x += v.x; s.y += v.y; s.z += v.z; s.w += v.w;
        ss.x += v.x * v.x; ss.y += v.y * v.y; ss.z += v.z * v.z; ss.w += v.w * v.w;
    }
    __shared__ float4 sh[256];
    sh[threadIdx.x] = s;
    __syncthreads();
    if (threadIdx.x < 16) {
        float4 tot = sh[threadIdx.x];
#pragma unroll
        for (int j = 1; j < 16; j++) {
            float4 o = sh[threadIdx.x + j * 16];
            tot.x += o.x; tot.y += o.y; tot.z += o.z; tot.w += o.w;
        }
        atomicAdd(&g_sum[threadIdx.x * 4 + 0], tot.x);
        atomicAdd(&g_sum[threadIdx.x * 4 + 1], tot.y);
        atomicAdd(&g_sum[threadIdx.x * 4 + 2], tot.z);
        atomicAdd(&g_sum[threadIdx.x * 4 + 3], tot.w);
    }
    __syncthreads();
    sh[threadIdx.x] = ss;
    __syncthreads();
    if (threadIdx.x < 16) {
        float4 tot = sh[threadIdx.x];
#pragma unroll
        for (int j = 1; j < 16; j++) {
            float4 o = sh[threadIdx.x + j * 16];
            tot.x += o.x; tot.y += o.y; tot.z += o.z; tot.w += o.w;
        }
        atomicAdd(&g_ssq[threadIdx.x * 4 + 0], tot.x);
        atomicAdd(&g_ssq[threadIdx.x * 4 + 1], tot.y);
        atomicAdd(&g_ssq[threadIdx.x * 4 + 2], tot.z);
        atomicAdd(&g_ssq[threadIdx.x * 4 + 3], tot.w);
    }
}

__global__ void k_bn_final(const float* __restrict__ gamma, const float* __restrict__ beta) {
    int f = threadIdx.x;
    float mu = g_sum[f] * (1.0f / NN);
    float var = g_ssq[f] * (1.0f / NN) - mu * mu;
    float a = gamma[f] * rsqrtf(var + BN_EPS);
    g_bna[f] = a;
    g_bnc[f] = beta[f] - mu * a;
}

__global__ void k_out(float* __restrict__ out) {
    int idx = blockIdx.x * blockDim.x + threadIdx.x;
    if (idx >= NN * (HID / 4)) return;
    int c4 = idx & 15;
    float4 h = ((const float4*)g_h0)[idx];
    float4 a = ((const float4*)g_bna)[c4];
    float4 c = ((const float4*)g_bnc)[c4];
    float4 r;
    r.x = h.x * a.x + c.x;
    r.y = h.y * a.y + c.y;
    r.z = h.z * a.z + c.z;
    r.w = h.w * a.w + c.w;
    ((float4*)out)[idx] = r;
}

// ---------------- launch ----------------
extern "C" void kernel_launch(void* const* d_in, const int* in_sizes, int n_in,
                              void* d_out, int out_size) {
    const int* src = (const int*)d_in[0];
    const int* dst = (const int*)d_in[1];
    const float* x = (const float*)d_in[2];
    const float* fc_w = (const float*)d_in[3];
    const float* fc_b = (const float*)d_in[4];
    const float* w1 = (const float*)d_in[5];
    const float* b1 = (const float*)d_in[6];
    const float* w2 = (const float*)d_in[7];
    const float* b2 = (const float*)d_in[8];
    const float* gamma = (const float*)d_in[9];
    const float* beta = (const float*)d_in[10];
    float* out = (float*)d_out;

    const int nb_vec = (NN * (HID / 4) + 255) / 256;     // 6250
    const int nb_edge = (NE + 255) / 256;
    const int nb_scat = (NE * (HID / 4) + 255) / 256;    // 50000
    const int nb_gemm = (NN + 127) / 128;                // 782

    k_init<<<nb_vec, 256>>>();
    k_degree<<<nb_edge, 256>>>(src, dst);

    // h0 = x @ fc_w + fc_b
    k_gemm<0><<<nb_gemm, 256>>>(x, fc_w, fc_b);

    // conv1
    k_gemm<1><<<nb_gemm, 256>>>(nullptr, w1, nullptr);   // t = (h0@w1)*dego^-1/2
    k_scatter<<<nb_scat, 256>>>(src, dst);
    k_combine1<<<nb_vec, 256>>>(b1);                     // h1 + re-zero agg

    // conv2
    k_gemm<2><<<nb_gemm, 256>>>(nullptr, w2, nullptr);   // t = (h1@w2)*dego^-1/2
    k_scatter<<<nb_scat, 256>>>(src, dst);
    k_combine2_bn<<<256, 256>>>(b2);                     // h2 -> g_h0, BN partials

    k_bn_final<<<1, 64>>>(gamma, beta);
    k_out<<<nb_vec, 256>>>(out);
}